// round 8
// baseline (speedup 1.0000x reference)
#include <cuda_runtime.h>

#define BB 4
#define NN 16384
#define SSZ 2048            // queries per batch (NEVENT)
#define DD 62
#define CC 64               // D + 2
#define KK 64               // NSAMPLE
#define NQ (BB*SSZ)         // 8192 total queries
#define NTASK (NQ/2)        // 4096 pair-tasks
#define MMM 8388608         // SSZ*KK*CC per batch
#define R2 0.01f

// ---- scratch (device globals; deterministic: fully overwritten per launch) ----
__device__ int    g_idx[NQ*KK];     // neighbor indices
__device__ float4 g_mean4[NQ*16];   // per-(query,channel) means
__device__ float  g_ss[NQ];         // per-query sum of squared centered
__device__ float  g_rstd[BB];       // 1/(std+1e-5) per batch
__device__ int    g_task;           // work-stealing cursor; 0 at launch start
                                    // (static zero-init; k_finalize resets it
                                    //  every launch, so each replay sees 0)

// ---------------------------------------------------------------------------
// K_A: PERSISTENT fused ball-query + stats. Warps steal pair-tasks (2 queries
// sharing one candidate stream -> 2 independent ballot/compaction chains per
// chunk). Stealing keeps all warps busy until the pool drains, fixing the
// single-wave tail collapse (R6 achieved-occ 30.5%). Assignment order does
// not affect any output value -> deterministic.
//
// Distance replicates reference fp32 op sequence exactly:
//   qn = qx*qx + qy*qy ; pn = px*px + py*py   (mul,mul,add — no contraction)
//   c  = fma(qy,py, qx*px)                    (einsum K-ascending chain)
//   d  = (qn + pn) - 2*c ;  hit iff !(d > R^2)
// ---------------------------------------------------------------------------
__global__ __launch_bounds__(128) void k_search_stats(
    const float* __restrict__ xy, const float* __restrict__ ev,
    const int* __restrict__ fps, float* __restrict__ out_xy, int write_xy)
{
    int w    = threadIdx.x >> 5;
    int lane = threadIdx.x & 31;
    unsigned lmask = (1u << lane) - 1u;

    __shared__ int sidx[4][2][KK];

    for (;;) {
        int task;
        if (lane == 0) task = atomicAdd(&g_task, 1);
        task = __shfl_sync(0xffffffffu, task, 0);
        if (task >= NTASK) break;

        int q0 = task * 2, q1 = q0 + 1;
        int b  = q0 >> 11;

        const float2* xyb  = reinterpret_cast<const float2*>(xy) + (size_t)b * NN;
        const float4* xyb4 = reinterpret_cast<const float4*>(xyb);

        float2 qa = xyb[fps[q0]];
        float2 qb = xyb[fps[q1]];
        float qna = __fadd_rn(__fmul_rn(qa.x, qa.x), __fmul_rn(qa.y, qa.y));
        float qnb = __fadd_rn(__fmul_rn(qb.x, qb.x), __fmul_rn(qb.y, qb.y));
        if (write_xy && lane == 0) {
            out_xy[2*q0] = qa.x; out_xy[2*q0+1] = qa.y;
            out_xy[2*q1] = qb.x; out_xy[2*q1+1] = qb.y;
        }

        // ---- search: 128 candidates/iter shared by both queries ----
        int cnt0 = 0, cnt1 = 0;                // warp-uniform
        float4 fa = xyb4[2*lane];
        float4 fb = xyb4[2*lane + 1];
        for (int j0 = 0; ; j0 += 128) {
            int jn = j0 + 128;
            bool more = (jn < NN);
            float4 na, nb;                     // prefetch next chunk
            if (more) {
                na = xyb4[(jn >> 1) + 2*lane];
                nb = xyb4[(jn >> 1) + 2*lane + 1];
            }
            float pn0 = __fadd_rn(__fmul_rn(fa.x, fa.x), __fmul_rn(fa.y, fa.y));
            float pn1 = __fadd_rn(__fmul_rn(fa.z, fa.z), __fmul_rn(fa.w, fa.w));
            float pn2 = __fadd_rn(__fmul_rn(fb.x, fb.x), __fmul_rn(fb.y, fb.y));
            float pn3 = __fadd_rn(__fmul_rn(fb.z, fb.z), __fmul_rn(fb.w, fb.w));
            int base = j0 + 4*lane;

            if (cnt0 < KK) {
                float c0 = __fmaf_rn(qa.y, fa.y, __fmul_rn(qa.x, fa.x));
                float c1 = __fmaf_rn(qa.y, fa.w, __fmul_rn(qa.x, fa.z));
                float c2 = __fmaf_rn(qa.y, fb.y, __fmul_rn(qa.x, fb.x));
                float c3 = __fmaf_rn(qa.y, fb.w, __fmul_rn(qa.x, fb.z));
                bool h0 = !(__fsub_rn(__fadd_rn(qna, pn0), __fmul_rn(2.0f, c0)) > R2);
                bool h1 = !(__fsub_rn(__fadd_rn(qna, pn1), __fmul_rn(2.0f, c1)) > R2);
                bool h2 = !(__fsub_rn(__fadd_rn(qna, pn2), __fmul_rn(2.0f, c2)) > R2);
                bool h3 = !(__fsub_rn(__fadd_rn(qna, pn3), __fmul_rn(2.0f, c3)) > R2);
                unsigned m0 = __ballot_sync(0xffffffffu, h0);
                unsigned m1 = __ballot_sync(0xffffffffu, h1);
                unsigned m2 = __ballot_sync(0xffffffffu, h2);
                unsigned m3 = __ballot_sync(0xffffffffu, h3);
                int pos = cnt0 + __popc(m0 & lmask) + __popc(m1 & lmask)
                               + __popc(m2 & lmask) + __popc(m3 & lmask);
                if (h0 && pos < KK) sidx[w][0][pos] = base;
                pos += h0 ? 1 : 0;
                if (h1 && pos < KK) sidx[w][0][pos] = base + 1;
                pos += h1 ? 1 : 0;
                if (h2 && pos < KK) sidx[w][0][pos] = base + 2;
                pos += h2 ? 1 : 0;
                if (h3 && pos < KK) sidx[w][0][pos] = base + 3;
                cnt0 += __popc(m0) + __popc(m1) + __popc(m2) + __popc(m3);
            }
            if (cnt1 < KK) {
                float c0 = __fmaf_rn(qb.y, fa.y, __fmul_rn(qb.x, fa.x));
                float c1 = __fmaf_rn(qb.y, fa.w, __fmul_rn(qb.x, fa.z));
                float c2 = __fmaf_rn(qb.y, fb.y, __fmul_rn(qb.x, fb.x));
                float c3 = __fmaf_rn(qb.y, fb.w, __fmul_rn(qb.x, fb.z));
                bool h0 = !(__fsub_rn(__fadd_rn(qnb, pn0), __fmul_rn(2.0f, c0)) > R2);
                bool h1 = !(__fsub_rn(__fadd_rn(qnb, pn1), __fmul_rn(2.0f, c1)) > R2);
                bool h2 = !(__fsub_rn(__fadd_rn(qnb, pn2), __fmul_rn(2.0f, c2)) > R2);
                bool h3 = !(__fsub_rn(__fadd_rn(qnb, pn3), __fmul_rn(2.0f, c3)) > R2);
                unsigned m0 = __ballot_sync(0xffffffffu, h0);
                unsigned m1 = __ballot_sync(0xffffffffu, h1);
                unsigned m2 = __ballot_sync(0xffffffffu, h2);
                unsigned m3 = __ballot_sync(0xffffffffu, h3);
                int pos = cnt1 + __popc(m0 & lmask) + __popc(m1 & lmask)
                               + __popc(m2 & lmask) + __popc(m3 & lmask);
                if (h0 && pos < KK) sidx[w][1][pos] = base;
                pos += h0 ? 1 : 0;
                if (h1 && pos < KK) sidx[w][1][pos] = base + 1;
                pos += h1 ? 1 : 0;
                if (h2 && pos < KK) sidx[w][1][pos] = base + 2;
                pos += h2 ? 1 : 0;
                if (h3 && pos < KK) sidx[w][1][pos] = base + 3;
                cnt1 += __popc(m0) + __popc(m1) + __popc(m2) + __popc(m3);
            }
            if ((cnt0 >= KK && cnt1 >= KK) || !more) break;
            fa = na; fb = nb;
        }
        __syncwarp();
        if (cnt0 < KK) {                       // pad (cnt>=1 always: self-hit)
            int f0 = sidx[w][0][0];
            for (int p = cnt0 + lane; p < KK; p += 32) sidx[w][0][p] = f0;
        }
        if (cnt1 < KK) {
            int f0 = sidx[w][1][0];
            for (int p = cnt1 + lane; p < KK; p += 32) sidx[w][1][p] = f0;
        }
        __syncwarp();

        // persist indices for k_write (coalesced)
        g_idx[(size_t)q0 * KK + lane]      = sidx[w][0][lane];
        g_idx[(size_t)q0 * KK + lane + 32] = sidx[w][0][lane + 32];
        g_idx[(size_t)q1 * KK + lane]      = sidx[w][1][lane];
        g_idx[(size_t)q1 * KK + lane + 32] = sidx[w][1][lane + 32];

        // ---- stats: both queries interleaved (2x MLP); lane = channel pair ----
        const float2* evb2 = reinterpret_cast<const float2*>(ev + (size_t)b * NN * DD);
        float2 s1a = make_float2(0.f,0.f), s2a = make_float2(0.f,0.f);
        float2 s1b = make_float2(0.f,0.f), s2b = make_float2(0.f,0.f);
        bool isxy = (lane == 31);
        #pragma unroll 8
        for (int k = 0; k < KK; k++) {
            int ja = sidx[w][0][k];
            int jb = sidx[w][1][k];
            float2 va = isxy ? xyb[ja] : evb2[(size_t)ja * 31 + lane];
            float2 vb = isxy ? xyb[jb] : evb2[(size_t)jb * 31 + lane];
            s1a.x += va.x; s1a.y += va.y;
            s2a.x = fmaf(va.x, va.x, s2a.x);
            s2a.y = fmaf(va.y, va.y, s2a.y);
            s1b.x += vb.x; s1b.y += vb.y;
            s2b.x = fmaf(vb.x, vb.x, s2b.x);
            s2b.y = fmaf(vb.y, vb.y, s2b.y);
        }
        float2 ma = make_float2(s1a.x * (1.0f/64.0f), s1a.y * (1.0f/64.0f));
        float2 mb = make_float2(s1b.x * (1.0f/64.0f), s1b.y * (1.0f/64.0f));
        reinterpret_cast<float2*>(g_mean4)[(size_t)q0 * 32 + lane] = ma;
        reinterpret_cast<float2*>(g_mean4)[(size_t)q1 * 32 + lane] = mb;
        float ssa = (s2a.x - s1a.x * ma.x) + (s2a.y - s1a.y * ma.y);
        float ssb = (s2b.x - s1b.x * mb.x) + (s2b.y - s1b.y * mb.y);
        #pragma unroll
        for (int off = 16; off >= 1; off >>= 1) {
            ssa += __shfl_down_sync(0xffffffffu, ssa, off);
            ssb += __shfl_down_sync(0xffffffffu, ssb, off);
        }
        if (lane == 0) { g_ss[q0] = ssa; g_ss[q1] = ssb; }
    }
}

// ---------------------------------------------------------------------------
// K_B: per-batch SS reduce -> rstd; also resets the work-stealing cursor for
// the next launch (runs after K_A consumed it -> every launch starts at 0).
// ---------------------------------------------------------------------------
__global__ __launch_bounds__(256) void k_finalize()
{
    int b = blockIdx.x, t = threadIdx.x;
    if (b == 0 && t == 0) g_task = 0;
    __shared__ float sh[256];
    float s = 0.f;
    #pragma unroll
    for (int i = 0; i < 8; i++) s += g_ss[(size_t)b * SSZ + t*8 + i];
    sh[t] = s;
    __syncthreads();
    for (int off = 128; off >= 1; off >>= 1) {
        if (t < off) sh[t] += sh[t + off];
        __syncthreads();
    }
    if (t == 0) {
        float var = sh[0] / (float)(MMM - 1);   // ddof = 1
        g_rstd[b] = 1.0f / (sqrtf(var) + 1e-5f);
    }
}

// ---------------------------------------------------------------------------
// K_C: regather + normalize + affine. Block per query; WARP per k-row:
// lane = channel pair (31 event pairs + 1 xy pair), so each gather touches a
// single 248B region (~3 L1 wavefronts) and each store is one coalesced 256B
// row. mean/alpha/beta live in per-lane registers. 8 rows per warp, unrolled.
// ---------------------------------------------------------------------------
__global__ __launch_bounds__(256) void k_write(
    const float* __restrict__ xy, const float* __restrict__ ev,
    const float* __restrict__ alpha, const float* __restrict__ beta,
    float* __restrict__ out_ev)
{
    int q = blockIdx.x;
    int b = q >> 11;
    int w = threadIdx.x >> 5, lane = threadIdx.x & 31;

    __shared__ int sidx[KK];
    if (threadIdx.x < KK) sidx[threadIdx.x] = g_idx[(size_t)q * KK + threadIdx.x];
    __syncthreads();

    float  rstd = g_rstd[b];
    float2 mean = reinterpret_cast<const float2*>(g_mean4)[(size_t)q * 32 + lane];
    float2 al   = reinterpret_cast<const float2*>(alpha)[lane];
    float2 be   = reinterpret_cast<const float2*>(beta)[lane];

    const float2* evb2 = reinterpret_cast<const float2*>(ev + (size_t)b * NN * DD);
    const float2* xyb  = reinterpret_cast<const float2*>(xy) + (size_t)b * NN;
    float2* op = reinterpret_cast<float2*>(out_ev) + (size_t)q * KK * 32;

    bool isxy = (lane == 31);
    #pragma unroll
    for (int ki = 0; ki < 8; ki++) {
        int k = ki * 8 + w;
        int j = sidx[k];
        float2 v = isxy ? xyb[j] : evb2[(size_t)j * 31 + lane];
        float2 r;
        r.x = fmaf(al.x, (v.x - mean.x) * rstd, be.x);
        r.y = fmaf(al.y, (v.y - mean.y) * rstd, be.y);
        op[(size_t)k * 32 + lane] = r;
    }
}

// ---------------------------------------------------------------------------
extern "C" void kernel_launch(void* const* d_in, const int* in_sizes, int n_in,
                              void* d_out, int out_size)
{
    const float* xy    = (const float*)d_in[0];
    const float* ev    = (const float*)d_in[1];
    const int*   fps   = (const int*)d_in[2];
    const float* alpha = (const float*)d_in[3];
    const float* beta  = (const float*)d_in[4];
    float* out = (float*)d_out;

    long long ev_elems = (long long)NQ * KK * CC;
    int has_xy = ((long long)out_size >= ev_elems + (long long)NQ * 2) ? 1 : 0;
    float* out_ev = out + (has_xy ? NQ * 2 : 0);

    k_search_stats<<<296, 128>>>(xy, ev, fps, out, has_xy);  // persistent, 2 blk/SM
    k_finalize    <<<BB,  256>>>();
    k_write       <<<NQ,  256>>>(xy, ev, alpha, beta, out_ev);
}